// round 16
// baseline (speedup 1.0000x reference)
#include <cuda_runtime.h>
#include <cuda_bf16.h>
#include <cstdint>

static constexpr int N = 50000;
static constexpr int E = 1600000;
static constexpr int SCAN_B = 1024;
static constexpr int NBLK = (N + SCAN_B - 1) / SCAN_B;   // 49

// ---------------- scratch -----------------------------------------------------
__device__ __align__(16) float g_h0[N * 128];
__device__ __align__(16) float g_h1[N * 128];
__device__ __align__(16) float g_mean[N * 128];
__device__ __align__(16) __nv_bfloat16 g_bB[N * 64];    // y2 bf16 shadow (layer-2 gather)
__device__ __align__(16) float g_Wr0[256 * 128];
__device__ __align__(16) float g_Wr1[256 * 128];
__device__ __align__(16) float g_Wr2x[128 * 128];       // [k][ z-cols | y-cols ]
__device__ float g_z[N * 64];
__device__ int   g_deg[N];     // zero at start of every call
__device__ int   g_row[N + 1];
__device__ int   g_fill[N];
__device__ __align__(16) int g_csr[E];
__device__ float g_inv[N];
__device__ unsigned long long g_part[NBLK];   // decoupled-lookback partials

__device__ __forceinline__ float to_tf32(float x) {
    uint32_t u;
    asm("cvt.rna.tf32.f32 %0, %1;" : "=r"(u) : "f"(x));
    return __uint_as_float(u);
}
__device__ __forceinline__ float4 ldnc_f4(const void* p) {
    float4 r;
    asm volatile("ld.global.nc.v4.f32 {%0,%1,%2,%3}, [%4];"
                 : "=f"(r.x), "=f"(r.y), "=f"(r.z), "=f"(r.w) : "l"(p));
    return r;
}
__device__ __forceinline__ uint32_t ldnc_u1(const void* p) {
    uint32_t r;
    asm volatile("ld.global.nc.u32 %0, [%1];" : "=r"(r) : "l"(p));
    return r;
}

// ---------------- merged prep + degree count ----------------------------------
__global__ void prep_count_k(const float* __restrict__ W0,
                             const float* __restrict__ W1,
                             const float* __restrict__ W2,
                             const int* __restrict__ dst) {
    int i = blockIdx.x * blockDim.x + threadIdx.x;
    if (i < E) atomicAdd(&g_deg[dst[i]], 1);
    if (i < 256 * 128) {
        g_Wr0[i] = to_tf32(W0[i]);
        g_Wr1[i] = to_tf32(W1[i]);
    }
    if (i < 128 * 128) {
        int k = i >> 7, n = i & 127;
        float v = (n < 64) ? W2[k * 64 + n] : W2[(128 + k) * 64 + (n - 64)];
        g_Wr2x[i] = to_tf32(v);
    }
}

// ---------------- fused scan: decoupled lookback ------------------------------
__global__ void __launch_bounds__(SCAN_B) scan_k() {
    __shared__ int wsum[32];
    __shared__ unsigned int soff;
    int tid = threadIdx.x, lane = tid & 31, wid = tid >> 5;
    int b = blockIdx.x;
    int i = b * SCAN_B + tid;
    int v = (i < N) ? g_deg[i] : 0;
    int x = v;
    #pragma unroll
    for (int o = 1; o < 32; o <<= 1) {
        int t = __shfl_up_sync(0xffffffffu, x, o);
        if (lane >= o) x += t;
    }
    if (lane == 31) wsum[wid] = x;
    __syncthreads();
    if (wid == 0) {
        int s = wsum[lane];
        #pragma unroll
        for (int o = 1; o < 32; o <<= 1) {
            int t = __shfl_up_sync(0xffffffffu, s, o);
            if (lane >= o) s += t;
        }
        wsum[lane] = s;
    }
    __syncthreads();
    int excl = x - v + (wid ? wsum[wid - 1] : 0);
    if (tid == 0) {
        unsigned long long pk = (1ull << 32) | (unsigned long long)(unsigned)wsum[31];
        atomicExch(&g_part[b], pk);
    }
    if (wid == 0) {
        unsigned long long acc = 0;
        for (int j = lane; j < b; j += 32) {
            unsigned long long p;
            do { p = atomicAdd(&g_part[j], 0ull); } while (!(p >> 32));
            acc += (unsigned)p;
        }
        #pragma unroll
        for (int o = 16; o; o >>= 1) acc += __shfl_down_sync(0xffffffffu, acc, o);
        if (lane == 0) soff = (unsigned)acc;
    }
    __syncthreads();
    if (i < N) {
        int r = excl + (int)soff;
        g_row[i] = r;
        g_fill[i] = r;
        g_inv[i] = 1.0f / (float)(v > 0 ? v : 1);
        g_deg[i] = 0;
    }
    if (b == 0 && tid == 0) g_row[N] = E;
}

__global__ void scatter_k(const int* __restrict__ src, const int* __restrict__ dst) {
    int i = blockIdx.x * blockDim.x + threadIdx.x;
    if (i < NBLK) g_part[i] = 0ull;
    if (i < E) {
        int pos = atomicAdd(&g_fill[dst[i]], 1);
        g_csr[pos] = src[i];
    }
}

// ---------------- aggregation (128-dim fp32 gather -> fp32 mean) --------------
// No unpack ALU: 1 LDG.128 + 4 FADD per edge. 8-deep unroll (32 data regs).
__global__ void __launch_bounds__(256)
agg_k(const float* __restrict__ h_in, int in_sel) {
    const float* h = (in_sel == 0) ? h_in : g_h0;
    int tid = threadIdx.x, lane = tid & 31, w = tid >> 5;
    int node = blockIdx.x * 8 + w;
    if (node >= N) return;
    int k4 = lane * 4;
    float4 acc = make_float4(0.f, 0.f, 0.f, 0.f);
    int beg = g_row[node], end = g_row[node + 1];
    int e = beg;
    int ae = (beg + 3) & ~3;
    if (ae > end) ae = end;
    for (; e < ae; ++e) {
        float4 r = ldnc_f4(h + g_csr[e] * 128 + k4);
        acc.x += r.x; acc.y += r.y; acc.z += r.z; acc.w += r.w;
    }
    for (; e + 8 <= end; e += 8) {
        int4 c0 = *(const int4*)(g_csr + e);
        int4 c1 = *(const int4*)(g_csr + e + 4);
        int s[8] = {c0.x, c0.y, c0.z, c0.w, c1.x, c1.y, c1.z, c1.w};
        float4 r[8];
        #pragma unroll
        for (int q = 0; q < 8; q++) r[q] = ldnc_f4(h + s[q] * 128 + k4);
        float x0 = 0.f, y0 = 0.f, z0 = 0.f, w0 = 0.f;
        #pragma unroll
        for (int q = 0; q < 8; q++) {
            x0 += r[q].x; y0 += r[q].y; z0 += r[q].z; w0 += r[q].w;
        }
        acc.x += x0; acc.y += y0; acc.z += z0; acc.w += w0;
    }
    for (; e + 4 <= end; e += 4) {
        int4 c = *(const int4*)(g_csr + e);
        int s[4] = {c.x, c.y, c.z, c.w};
        float4 r[4];
        #pragma unroll
        for (int q = 0; q < 4; q++) r[q] = ldnc_f4(h + s[q] * 128 + k4);
        #pragma unroll
        for (int q = 0; q < 4; q++) {
            acc.x += r[q].x; acc.y += r[q].y; acc.z += r[q].z; acc.w += r[q].w;
        }
    }
    for (; e < end; ++e) {
        float4 r = ldnc_f4(h + g_csr[e] * 128 + k4);
        acc.x += r.x; acc.y += r.y; acc.z += r.z; acc.w += r.w;
    }
    float idg = g_inv[node];
    acc.x *= idg; acc.y *= idg; acc.z *= idg; acc.w *= idg;
    *(float4*)(g_mean + node * 128 + k4) = acc;
}

// ---- layer-2 final: 64-dim bf16 gather of y2, fused add with z2 -> out -------
__global__ void __launch_bounds__(256)
agg64_k(float* __restrict__ out) {
    int tid = threadIdx.x, lane = tid & 31, w = tid >> 5;
    int node = blockIdx.x * 8 + w;
    if (node >= N) return;
    int k2 = lane * 2;
    float ax = 0.f, ay = 0.f;
    int beg = g_row[node], end = g_row[node + 1];
    int e = beg;
    int ae = (beg + 3) & ~3;
    if (ae > end) ae = end;
    for (; e < ae; ++e) {
        uint32_t r = ldnc_u1(g_bB + g_csr[e] * 64 + k2);
        ax += __uint_as_float(r << 16);
        ay += __uint_as_float(r & 0xffff0000u);
    }
    for (; e + 16 <= end; e += 16) {
        int4 c0 = *(const int4*)(g_csr + e);
        int4 c1 = *(const int4*)(g_csr + e + 4);
        int4 c2 = *(const int4*)(g_csr + e + 8);
        int4 c3 = *(const int4*)(g_csr + e + 12);
        int s[16] = {c0.x, c0.y, c0.z, c0.w, c1.x, c1.y, c1.z, c1.w,
                     c2.x, c2.y, c2.z, c2.w, c3.x, c3.y, c3.z, c3.w};
        uint32_t r[16];
        #pragma unroll
        for (int q = 0; q < 16; q++) r[q] = ldnc_u1(g_bB + s[q] * 64 + k2);
        float x0 = 0.f, y0 = 0.f;
        #pragma unroll
        for (int q = 0; q < 16; q++) {
            x0 += __uint_as_float(r[q] << 16);
            y0 += __uint_as_float(r[q] & 0xffff0000u);
        }
        ax += x0; ay += y0;
    }
    for (; e + 4 <= end; e += 4) {
        int4 c = *(const int4*)(g_csr + e);
        int s[4] = {c.x, c.y, c.z, c.w};
        uint32_t r[4];
        #pragma unroll
        for (int q = 0; q < 4; q++) r[q] = ldnc_u1(g_bB + s[q] * 64 + k2);
        #pragma unroll
        for (int q = 0; q < 4; q++) {
            ax += __uint_as_float(r[q] << 16);
            ay += __uint_as_float(r[q] & 0xffff0000u);
        }
    }
    for (; e < end; ++e) {
        uint32_t r = ldnc_u1(g_bB + g_csr[e] * 64 + k2);
        ax += __uint_as_float(r << 16);
        ay += __uint_as_float(r & 0xffff0000u);
    }
    float idg = g_inv[node];
    float2 z = *(const float2*)(g_z + node * 64 + k2);
    *(float2*)(out + node * 64 + k2) = make_float2(z.x + ax * idg, z.y + ay * idg);
}

// ---------------- tf32 mma.sync GEMM (layers 0,1) -----------------------------
template <int FOUT, bool RELU>
__global__ void __launch_bounds__(256)
gemm_k(const float* __restrict__ hself_p, int self_sel,
       const float* __restrict__ bias,
       int out_sel, int wsel) {
    const float* hs = (self_sel == 0) ? hself_p : g_h0;
    float* of = (out_sel == 1) ? g_h0 : g_h1;
    const float* Wr = (wsel == 0) ? g_Wr0 : g_Wr1;

    constexpr int WP = FOUT + 8;
    constexpr int AP = 132;
    constexpr int NT = FOUT / 32;
    extern __shared__ float smem[];
    float* sW = smem;
    float* sA = smem + 128 * WP;

    int tid = threadIdx.x, lane = tid & 31, w = tid >> 5;
    int g = lane >> 2, tg = lane & 3;
    int wm = w & 1, wn = w >> 1;
    int node_base = blockIdx.x * 64;

    float c[2][NT][4];
    #pragma unroll
    for (int mt = 0; mt < 2; mt++)
        #pragma unroll
        for (int nt = 0; nt < NT; nt++)
            #pragma unroll
            for (int i = 0; i < 4; i++) c[mt][nt][i] = 0.f;

    #pragma unroll
    for (int half = 0; half < 2; half++) {
        const float* srcW = Wr + half * 128 * FOUT;
        for (int idx = tid; idx < 128 * (FOUT / 4); idx += 256) {
            int k = idx / (FOUT / 4);
            int c4 = (idx % (FOUT / 4)) * 4;
            float4 v = *(const float4*)(srcW + k * FOUT + c4);
            *(float4*)(sW + k * WP + c4) = v;
        }
        const float* srcA = (half == 0) ? hs : g_mean;
        for (int idx = tid; idx < 64 * 32; idx += 256) {
            int r = idx >> 5;
            int c4 = (idx & 31) << 2;
            int node = node_base + r;
            float4 v = make_float4(0.f, 0.f, 0.f, 0.f);
            if (node < N) v = *(const float4*)(srcA + node * 128 + c4);
            v.x = to_tf32(v.x); v.y = to_tf32(v.y);
            v.z = to_tf32(v.z); v.w = to_tf32(v.w);
            *(float4*)(sA + r * AP + c4) = v;
        }
        __syncthreads();

        #pragma unroll 4
        for (int s = 0; s < 16; s++) {
            int k = s * 8;
            uint32_t a[2][4];
            #pragma unroll
            for (int mt = 0; mt < 2; mt++) {
                int r0 = wm * 32 + mt * 16 + g;
                a[mt][0] = __float_as_uint(sA[r0 * AP + k + tg]);
                a[mt][1] = __float_as_uint(sA[(r0 + 8) * AP + k + tg]);
                a[mt][2] = __float_as_uint(sA[r0 * AP + k + tg + 4]);
                a[mt][3] = __float_as_uint(sA[(r0 + 8) * AP + k + tg + 4]);
            }
            #pragma unroll
            for (int nt = 0; nt < NT; nt++) {
                int col = wn * (FOUT / 4) + nt * 8 + g;
                uint32_t b0 = __float_as_uint(sW[(k + tg) * WP + col]);
                uint32_t b1 = __float_as_uint(sW[(k + tg + 4) * WP + col]);
                #pragma unroll
                for (int mt = 0; mt < 2; mt++) {
                    asm volatile(
                        "mma.sync.aligned.m16n8k8.row.col.f32.tf32.tf32.f32 "
                        "{%0,%1,%2,%3}, {%4,%5,%6,%7}, {%8,%9}, {%0,%1,%2,%3};"
                        : "+f"(c[mt][nt][0]), "+f"(c[mt][nt][1]),
                          "+f"(c[mt][nt][2]), "+f"(c[mt][nt][3])
                        : "r"(a[mt][0]), "r"(a[mt][1]), "r"(a[mt][2]), "r"(a[mt][3]),
                          "r"(b0), "r"(b1));
                }
            }
        }
        __syncthreads();
    }

    #pragma unroll
    for (int nt = 0; nt < NT; nt++) {
        int col = wn * (FOUT / 4) + nt * 8 + tg * 2;
        float bx = __ldg(bias + col), by = __ldg(bias + col + 1);
        #pragma unroll
        for (int mt = 0; mt < 2; mt++) {
            #pragma unroll
            for (int hrow = 0; hrow < 2; hrow++) {
                int node = node_base + wm * 32 + mt * 16 + g + hrow * 8;
                if (node >= N) continue;
                float ox = c[mt][nt][hrow * 2 + 0] + bx;
                float oy = c[mt][nt][hrow * 2 + 1] + by;
                if (RELU) { ox = fmaxf(ox, 0.f); oy = fmaxf(oy, 0.f); }
                *(float2*)(of + node * FOUT + col) = make_float2(ox, oy);
            }
        }
    }
}

// ---------------- layer-2 GEMM: [z2|y2] = h2 @ [W2_top|W2_bot] -----------------
__global__ void __launch_bounds__(256)
gemm2x_k(const float* __restrict__ bias) {
    constexpr int WP = 136;
    constexpr int AP = 132;
    extern __shared__ float smem[];
    float* sW = smem;
    float* sA = smem + 128 * WP;

    int tid = threadIdx.x, lane = tid & 31, w = tid >> 5;
    int g = lane >> 2, tg = lane & 3;
    int wm = w & 1, wn = w >> 1;
    int node_base = blockIdx.x * 64;

    float c[2][4][4];
    #pragma unroll
    for (int mt = 0; mt < 2; mt++)
        #pragma unroll
        for (int nt = 0; nt < 4; nt++)
            #pragma unroll
            for (int i = 0; i < 4; i++) c[mt][nt][i] = 0.f;

    for (int idx = tid; idx < 128 * 32; idx += 256) {
        int k = idx >> 5;
        int c4 = (idx & 31) << 2;
        float4 v = *(const float4*)(g_Wr2x + k * 128 + c4);
        *(float4*)(sW + k * WP + c4) = v;
    }
    for (int idx = tid; idx < 64 * 32; idx += 256) {
        int r = idx >> 5;
        int c4 = (idx & 31) << 2;
        int node = node_base + r;
        float4 v = make_float4(0.f, 0.f, 0.f, 0.f);
        if (node < N) v = *(const float4*)(g_h1 + node * 128 + c4);
        v.x = to_tf32(v.x); v.y = to_tf32(v.y);
        v.z = to_tf32(v.z); v.w = to_tf32(v.w);
        *(float4*)(sA + r * AP + c4) = v;
    }
    __syncthreads();

    #pragma unroll 4
    for (int s = 0; s < 16; s++) {
        int k = s * 8;
        uint32_t a[2][4];
        #pragma unroll
        for (int mt = 0; mt < 2; mt++) {
            int r0 = wm * 32 + mt * 16 + g;
            a[mt][0] = __float_as_uint(sA[r0 * AP + k + tg]);
            a[mt][1] = __float_as_uint(sA[(r0 + 8) * AP + k + tg]);
            a[mt][2] = __float_as_uint(sA[r0 * AP + k + tg + 4]);
            a[mt][3] = __float_as_uint(sA[(r0 + 8) * AP + k + tg + 4]);
        }
        #pragma unroll
        for (int nt = 0; nt < 4; nt++) {
            int col = wn * 32 + nt * 8 + g;
            uint32_t b0 = __float_as_uint(sW[(k + tg) * WP + col]);
            uint32_t b1 = __float_as_uint(sW[(k + tg + 4) * WP + col]);
            #pragma unroll
            for (int mt = 0; mt < 2; mt++) {
                asm volatile(
                    "mma.sync.aligned.m16n8k8.row.col.f32.tf32.tf32.f32 "
                    "{%0,%1,%2,%3}, {%4,%5,%6,%7}, {%8,%9}, {%0,%1,%2,%3};"
                    : "+f"(c[mt][nt][0]), "+f"(c[mt][nt][1]),
                      "+f"(c[mt][nt][2]), "+f"(c[mt][nt][3])
                    : "r"(a[mt][0]), "r"(a[mt][1]), "r"(a[mt][2]), "r"(a[mt][3]),
                      "r"(b0), "r"(b1));
            }
        }
    }

    #pragma unroll
    for (int nt = 0; nt < 4; nt++) {
        int col = wn * 32 + nt * 8 + tg * 2;
        bool zcol = (col < 64);
        float bx = zcol ? __ldg(bias + col) : 0.f;
        float by = zcol ? __ldg(bias + col + 1) : 0.f;
        #pragma unroll
        for (int mt = 0; mt < 2; mt++) {
            #pragma unroll
            for (int hrow = 0; hrow < 2; hrow++) {
                int node = node_base + wm * 32 + mt * 16 + g + hrow * 8;
                if (node >= N) continue;
                float ox = c[mt][nt][hrow * 2 + 0] + bx;
                float oy = c[mt][nt][hrow * 2 + 1] + by;
                if (zcol) {
                    *(float2*)(g_z + node * 64 + col) = make_float2(ox, oy);
                } else {
                    __nv_bfloat162 p = __float22bfloat162_rn(make_float2(ox, oy));
                    *(__nv_bfloat162*)(g_bB + node * 64 + (col - 64)) = p;
                }
            }
        }
    }
}

// ---------------- launcher ----------------------------------------------------
extern "C" void kernel_launch(void* const* d_in, const int* in_sizes, int n_in,
                              void* d_out, int out_size) {
    const float* feat = (const float*)d_in[0];
    const int*   src  = (const int*)d_in[1];
    const int*   dst  = (const int*)d_in[2];
    const float* W0   = (const float*)d_in[3];
    const float* b0   = (const float*)d_in[4];
    const float* W1   = (const float*)d_in[5];
    const float* b1   = (const float*)d_in[6];
    const float* W2   = (const float*)d_in[7];
    const float* b2   = (const float*)d_in[8];
    float* out = (float*)d_out;

    const int smem128 = (128 * 136 + 64 * 132) * 4;   // 103,424 B
    cudaFuncSetAttribute(gemm_k<128, true>, cudaFuncAttributeMaxDynamicSharedMemorySize, smem128);
    cudaFuncSetAttribute(gemm2x_k, cudaFuncAttributeMaxDynamicSharedMemorySize, smem128);

    const int TB = 256;
    prep_count_k<<<(E + TB - 1) / TB, TB>>>(W0, W1, W2, dst);
    scan_k<<<NBLK, SCAN_B>>>();
    scatter_k<<<(E + TB - 1) / TB, TB>>>(src, dst);

    int ablocks = (N + 7) / 8;       // 6250
    int gblocks = (N + 63) / 64;     // 782

    // layer 0: fp32 gather of feat
    agg_k<<<ablocks, TB>>>(feat, 0);
    gemm_k<128, true><<<gblocks, TB, smem128>>>(feat, 0, b0, 1, 0);
    // layer 1: fp32 gather of g_h0
    agg_k<<<ablocks, TB>>>(nullptr, 1);
    gemm_k<128, true><<<gblocks, TB, smem128>>>(nullptr, 1, b1, 2, 1);
    // layer 2 (projection-first): [z2|y2] = h2 @ [W2_top|W2_bot]; 64-dim bf16 gather + add
    gemm2x_k<<<gblocks, TB, smem128>>>(b2);
    agg64_k<<<ablocks, TB>>>(out);
}

// round 17
// speedup vs baseline: 1.0859x; 1.0859x over previous
#include <cuda_runtime.h>
#include <cuda_bf16.h>
#include <cstdint>

static constexpr int N = 50000;
static constexpr int E = 1600000;
static constexpr int SCAN_B = 1024;
static constexpr int NBLK = (N + SCAN_B - 1) / SCAN_B;   // 49

// ---------------- scratch -----------------------------------------------------
__device__ __align__(16) float g_h0[N * 128];
__device__ __align__(16) float g_h1[N * 128];
__device__ __align__(16) float g_mean[N * 128];
__device__ __align__(16) __nv_bfloat16 g_bA[N * 128];   // bf16 feat shadow
__device__ __align__(16) __nv_bfloat16 g_bB[N * 128];   // layer0-out shadow / y2 shadow
__device__ __align__(16) float g_Wr0[256 * 128];
__device__ __align__(16) float g_Wr1[256 * 128];
__device__ __align__(16) float g_Wr2x[128 * 128];       // [k][ z-cols | y-cols ]
__device__ float g_z[N * 64];
__device__ int   g_deg[N];     // zero at start of every call
__device__ int   g_row[N + 1];
__device__ int   g_fill[N];
__device__ __align__(16) int g_csr[E];
__device__ float g_inv[N];
__device__ int   g_bsum[NBLK];

__device__ __forceinline__ float to_tf32(float x) {
    uint32_t u;
    asm("cvt.rna.tf32.f32 %0, %1;" : "=r"(u) : "f"(x));
    return __uint_as_float(u);
}
__device__ __forceinline__ uint2 ldnc_u2(const void* p) {
    uint2 r;
    asm volatile("ld.global.nc.v2.u32 {%0,%1}, [%2];" : "=r"(r.x), "=r"(r.y) : "l"(p));
    return r;
}
__device__ __forceinline__ uint32_t ldnc_u1(const void* p) {
    uint32_t r;
    asm volatile("ld.global.nc.u32 %0, [%1];" : "=r"(r) : "l"(p));
    return r;
}
// packed accumulate: a(f32x2) += (bf16lo(r), bf16hi(r)) — identical arithmetic
// to two scalar FADDs (f32x2 = 2 independent fp32 lanes), 6 ops/uint2 vs 8.
__device__ __forceinline__ void addp(unsigned long long& a, uint32_t r) {
    unsigned long long p;
    uint32_t lo = r << 16;
    uint32_t hi = r & 0xffff0000u;
    asm("mov.b64 %0, {%1, %2};" : "=l"(p) : "r"(lo), "r"(hi));
    asm("add.rn.f32x2 %0, %0, %1;" : "+l"(a) : "l"(p));
}
__device__ __forceinline__ float2 unpk(unsigned long long a) {
    float2 v;
    asm("mov.b64 {%0, %1}, %2;" : "=f"(v.x), "=f"(v.y) : "l"(a));
    return v;
}

// ---------------- merged prep + degree count ----------------------------------
__global__ void prep_count_k(const float* __restrict__ f,
                             const float* __restrict__ W0,
                             const float* __restrict__ W1,
                             const float* __restrict__ W2,
                             const int* __restrict__ dst) {
    int i = blockIdx.x * blockDim.x + threadIdx.x;
    if (i < E) atomicAdd(&g_deg[dst[i]], 1);
    if (i < N * 64) {
        float2 v = ((const float2*)f)[i];
        ((__nv_bfloat162*)g_bA)[i] = __float22bfloat162_rn(v);
    }
    if (i < 256 * 128) {
        g_Wr0[i] = to_tf32(W0[i]);
        g_Wr1[i] = to_tf32(W1[i]);
    }
    if (i < 128 * 128) {
        int k = i >> 7, n = i & 127;
        float v = (n < 64) ? W2[k * 64 + n] : W2[(128 + k) * 64 + (n - 64)];
        g_Wr2x[i] = to_tf32(v);
    }
}

// block-local exclusive scan of g_deg -> g_row; block sums
__global__ void __launch_bounds__(SCAN_B) scanA_k() {
    __shared__ int wsum[32];
    int tid = threadIdx.x, lane = tid & 31, wid = tid >> 5;
    int i = blockIdx.x * SCAN_B + tid;
    int v = (i < N) ? g_deg[i] : 0;
    int x = v;
    #pragma unroll
    for (int o = 1; o < 32; o <<= 1) {
        int t = __shfl_up_sync(0xffffffffu, x, o);
        if (lane >= o) x += t;
    }
    if (lane == 31) wsum[wid] = x;
    __syncthreads();
    if (wid == 0) {
        int s = wsum[lane];
        #pragma unroll
        for (int o = 1; o < 32; o <<= 1) {
            int t = __shfl_up_sync(0xffffffffu, s, o);
            if (lane >= o) s += t;
        }
        wsum[lane] = s;
    }
    __syncthreads();
    int excl = x - v + (wid ? wsum[wid - 1] : 0);
    if (i < N) g_row[i] = excl;
    if (tid == SCAN_B - 1) g_bsum[blockIdx.x] = wsum[31];
}

// scanC: per-block redundant prefix of block sums; writes row/fill/inv; re-zeroes deg
__global__ void __launch_bounds__(SCAN_B) scanC_k() {
    __shared__ int pre[NBLK];
    int tid = threadIdx.x;
    if (tid < NBLK) pre[tid] = g_bsum[tid];
    __syncthreads();
    if (tid == 0) {
        int run = 0;
        #pragma unroll 7
        for (int b = 0; b < NBLK; b++) {
            int v = pre[b];
            pre[b] = run;
            run += v;
        }
    }
    __syncthreads();
    int i = blockIdx.x * SCAN_B + tid;
    if (i < N) {
        int r = g_row[i] + pre[blockIdx.x];
        g_row[i] = r;
        g_fill[i] = r;
        int d = g_deg[i];
        g_inv[i] = 1.0f / (float)(d > 0 ? d : 1);
        g_deg[i] = 0;
    }
    if (blockIdx.x == 0 && tid == 0) g_row[N] = E;
}

__global__ void scatter_k(const int* __restrict__ src, const int* __restrict__ dst) {
    int i = blockIdx.x * blockDim.x + threadIdx.x;
    if (i < E) {
        int pos = atomicAdd(&g_fill[dst[i]], 1);
        g_csr[pos] = src[i];
    }
}

// ---------------- aggregation (128-dim bf16 gather, packed f32x2 adds) --------
__global__ void __launch_bounds__(256)
agg_k(int gat_sel) {
    const __nv_bfloat16* h = (gat_sel == 0) ? g_bA : g_bB;
    int tid = threadIdx.x, lane = tid & 31, w = tid >> 5;
    int node = blockIdx.x * 8 + w;
    if (node >= N) return;
    int k4 = lane * 4;
    unsigned long long axy = 0ull, azw = 0ull;   // packed (x,y) and (z,w) fp32 pairs
    int beg = g_row[node], end = g_row[node + 1];
    int e = beg;
    for (; e + 16 <= end; e += 16) {
        int s[16];
        #pragma unroll
        for (int q = 0; q < 16; q++) s[q] = g_csr[e + q];
        uint2 r[16];
        #pragma unroll
        for (int q = 0; q < 16; q++) r[q] = ldnc_u2(h + s[q] * 128 + k4);
        #pragma unroll
        for (int q = 0; q < 16; q++) {
            addp(axy, r[q].x);
            addp(azw, r[q].y);
        }
    }
    for (; e + 4 <= end; e += 4) {
        int s[4];
        #pragma unroll
        for (int q = 0; q < 4; q++) s[q] = g_csr[e + q];
        uint2 r[4];
        #pragma unroll
        for (int q = 0; q < 4; q++) r[q] = ldnc_u2(h + s[q] * 128 + k4);
        #pragma unroll
        for (int q = 0; q < 4; q++) {
            addp(axy, r[q].x);
            addp(azw, r[q].y);
        }
    }
    for (; e < end; ++e) {
        uint2 r = ldnc_u2(h + g_csr[e] * 128 + k4);
        addp(axy, r.x);
        addp(azw, r.y);
    }
    float idg = g_inv[node];
    float2 xy = unpk(axy), zw = unpk(azw);
    float4 acc = make_float4(xy.x * idg, xy.y * idg, zw.x * idg, zw.y * idg);
    *(float4*)(g_mean + node * 128 + k4) = acc;
}

// ---- layer-2 final: 64-dim bf16 gather of y2, fused add with z2 -> out -------
__global__ void __launch_bounds__(256)
agg64_k(float* __restrict__ out) {
    int tid = threadIdx.x, lane = tid & 31, w = tid >> 5;
    int node = blockIdx.x * 8 + w;
    if (node >= N) return;
    int k2 = lane * 2;
    unsigned long long axy = 0ull;
    int beg = g_row[node], end = g_row[node + 1];
    int e = beg;
    for (; e + 16 <= end; e += 16) {
        int s[16];
        #pragma unroll
        for (int q = 0; q < 16; q++) s[q] = g_csr[e + q];
        uint32_t r[16];
        #pragma unroll
        for (int q = 0; q < 16; q++) r[q] = ldnc_u1(g_bB + s[q] * 64 + k2);
        #pragma unroll
        for (int q = 0; q < 16; q++) addp(axy, r[q]);
    }
    for (; e + 4 <= end; e += 4) {
        int s[4];
        #pragma unroll
        for (int q = 0; q < 4; q++) s[q] = g_csr[e + q];
        uint32_t r[4];
        #pragma unroll
        for (int q = 0; q < 4; q++) r[q] = ldnc_u1(g_bB + s[q] * 64 + k2);
        #pragma unroll
        for (int q = 0; q < 4; q++) addp(axy, r[q]);
    }
    for (; e < end; ++e) addp(axy, ldnc_u1(g_bB + g_csr[e] * 64 + k2));
    float idg = g_inv[node];
    float2 a = unpk(axy);
    float2 z = *(const float2*)(g_z + node * 64 + k2);
    *(float2*)(out + node * 64 + k2) = make_float2(z.x + a.x * idg, z.y + a.y * idg);
}

// ---------------- tf32 mma.sync GEMM (layers 0,1) -----------------------------
template <int FOUT, bool RELU, int SHADOW>
__global__ void __launch_bounds__(256)
gemm_k(const float* __restrict__ hself_p, int self_sel,
       const float* __restrict__ bias,
       int out_sel, int wsel) {
    const float* hs = (self_sel == 0) ? hself_p : g_h0;
    float* of = (out_sel == 1) ? g_h0 : g_h1;
    const float* Wr = (wsel == 0) ? g_Wr0 : g_Wr1;

    constexpr int WP = FOUT + 8;
    constexpr int AP = 132;
    constexpr int NT = FOUT / 32;
    extern __shared__ float smem[];
    float* sW = smem;
    float* sA = smem + 128 * WP;

    int tid = threadIdx.x, lane = tid & 31, w = tid >> 5;
    int g = lane >> 2, tg = lane & 3;
    int wm = w & 1, wn = w >> 1;
    int node_base = blockIdx.x * 64;

    float c[2][NT][4];
    #pragma unroll
    for (int mt = 0; mt < 2; mt++)
        #pragma unroll
        for (int nt = 0; nt < NT; nt++)
            #pragma unroll
            for (int i = 0; i < 4; i++) c[mt][nt][i] = 0.f;

    #pragma unroll
    for (int half = 0; half < 2; half++) {
        const float* srcW = Wr + half * 128 * FOUT;
        for (int idx = tid; idx < 128 * (FOUT / 4); idx += 256) {
            int k = idx / (FOUT / 4);
            int c4 = (idx % (FOUT / 4)) * 4;
            float4 v = *(const float4*)(srcW + k * FOUT + c4);
            *(float4*)(sW + k * WP + c4) = v;
        }
        const float* srcA = (half == 0) ? hs : g_mean;
        for (int idx = tid; idx < 64 * 32; idx += 256) {
            int r = idx >> 5;
            int c4 = (idx & 31) << 2;
            int node = node_base + r;
            float4 v = make_float4(0.f, 0.f, 0.f, 0.f);
            if (node < N) v = *(const float4*)(srcA + node * 128 + c4);
            v.x = to_tf32(v.x); v.y = to_tf32(v.y);
            v.z = to_tf32(v.z); v.w = to_tf32(v.w);
            *(float4*)(sA + r * AP + c4) = v;
        }
        __syncthreads();

        #pragma unroll 4
        for (int s = 0; s < 16; s++) {
            int k = s * 8;
            uint32_t a[2][4];
            #pragma unroll
            for (int mt = 0; mt < 2; mt++) {
                int r0 = wm * 32 + mt * 16 + g;
                a[mt][0] = __float_as_uint(sA[r0 * AP + k + tg]);
                a[mt][1] = __float_as_uint(sA[(r0 + 8) * AP + k + tg]);
                a[mt][2] = __float_as_uint(sA[r0 * AP + k + tg + 4]);
                a[mt][3] = __float_as_uint(sA[(r0 + 8) * AP + k + tg + 4]);
            }
            #pragma unroll
            for (int nt = 0; nt < NT; nt++) {
                int col = wn * (FOUT / 4) + nt * 8 + g;
                uint32_t b0 = __float_as_uint(sW[(k + tg) * WP + col]);
                uint32_t b1 = __float_as_uint(sW[(k + tg + 4) * WP + col]);
                #pragma unroll
                for (int mt = 0; mt < 2; mt++) {
                    asm volatile(
                        "mma.sync.aligned.m16n8k8.row.col.f32.tf32.tf32.f32 "
                        "{%0,%1,%2,%3}, {%4,%5,%6,%7}, {%8,%9}, {%0,%1,%2,%3};"
                        : "+f"(c[mt][nt][0]), "+f"(c[mt][nt][1]),
                          "+f"(c[mt][nt][2]), "+f"(c[mt][nt][3])
                        : "r"(a[mt][0]), "r"(a[mt][1]), "r"(a[mt][2]), "r"(a[mt][3]),
                          "r"(b0), "r"(b1));
                }
            }
        }
        __syncthreads();
    }

    #pragma unroll
    for (int nt = 0; nt < NT; nt++) {
        int col = wn * (FOUT / 4) + nt * 8 + tg * 2;
        float bx = __ldg(bias + col), by = __ldg(bias + col + 1);
        #pragma unroll
        for (int mt = 0; mt < 2; mt++) {
            #pragma unroll
            for (int hrow = 0; hrow < 2; hrow++) {
                int node = node_base + wm * 32 + mt * 16 + g + hrow * 8;
                if (node >= N) continue;
                float ox = c[mt][nt][hrow * 2 + 0] + bx;
                float oy = c[mt][nt][hrow * 2 + 1] + by;
                if (RELU) { ox = fmaxf(ox, 0.f); oy = fmaxf(oy, 0.f); }
                *(float2*)(of + node * FOUT + col) = make_float2(ox, oy);
                if (SHADOW == 1) {
                    __nv_bfloat162 p = __float22bfloat162_rn(make_float2(ox, oy));
                    *(__nv_bfloat162*)(g_bB + node * 128 + col) = p;
                }
            }
        }
    }
}

// ---------------- layer-2 GEMM: [z2|y2] = h2 @ [W2_top|W2_bot] -----------------
__global__ void __launch_bounds__(256)
gemm2x_k(const float* __restrict__ bias) {
    constexpr int WP = 136;
    constexpr int AP = 132;
    extern __shared__ float smem[];
    float* sW = smem;
    float* sA = smem + 128 * WP;

    int tid = threadIdx.x, lane = tid & 31, w = tid >> 5;
    int g = lane >> 2, tg = lane & 3;
    int wm = w & 1, wn = w >> 1;
    int node_base = blockIdx.x * 64;

    float c[2][4][4];
    #pragma unroll
    for (int mt = 0; mt < 2; mt++)
        #pragma unroll
        for (int nt = 0; nt < 4; nt++)
            #pragma unroll
            for (int i = 0; i < 4; i++) c[mt][nt][i] = 0.f;

    for (int idx = tid; idx < 128 * 32; idx += 256) {
        int k = idx >> 5;
        int c4 = (idx & 31) << 2;
        float4 v = *(const float4*)(g_Wr2x + k * 128 + c4);
        *(float4*)(sW + k * WP + c4) = v;
    }
    for (int idx = tid; idx < 64 * 32; idx += 256) {
        int r = idx >> 5;
        int c4 = (idx & 31) << 2;
        int node = node_base + r;
        float4 v = make_float4(0.f, 0.f, 0.f, 0.f);
        if (node < N) v = *(const float4*)(g_h1 + node * 128 + c4);
        v.x = to_tf32(v.x); v.y = to_tf32(v.y);
        v.z = to_tf32(v.z); v.w = to_tf32(v.w);
        *(float4*)(sA + r * AP + c4) = v;
    }
    __syncthreads();

    #pragma unroll 4
    for (int s = 0; s < 16; s++) {
        int k = s * 8;
        uint32_t a[2][4];
        #pragma unroll
        for (int mt = 0; mt < 2; mt++) {
            int r0 = wm * 32 + mt * 16 + g;
            a[mt][0] = __float_as_uint(sA[r0 * AP + k + tg]);
            a[mt][1] = __float_as_uint(sA[(r0 + 8) * AP + k + tg]);
            a[mt][2] = __float_as_uint(sA[r0 * AP + k + tg + 4]);
            a[mt][3] = __float_as_uint(sA[(r0 + 8) * AP + k + tg + 4]);
        }
        #pragma unroll
        for (int nt = 0; nt < 4; nt++) {
            int col = wn * 32 + nt * 8 + g;
            uint32_t b0 = __float_as_uint(sW[(k + tg) * WP + col]);
            uint32_t b1 = __float_as_uint(sW[(k + tg + 4) * WP + col]);
            #pragma unroll
            for (int mt = 0; mt < 2; mt++) {
                asm volatile(
                    "mma.sync.aligned.m16n8k8.row.col.f32.tf32.tf32.f32 "
                    "{%0,%1,%2,%3}, {%4,%5,%6,%7}, {%8,%9}, {%0,%1,%2,%3};"
                    : "+f"(c[mt][nt][0]), "+f"(c[mt][nt][1]),
                      "+f"(c[mt][nt][2]), "+f"(c[mt][nt][3])
                    : "r"(a[mt][0]), "r"(a[mt][1]), "r"(a[mt][2]), "r"(a[mt][3]),
                      "r"(b0), "r"(b1));
            }
        }
    }

    #pragma unroll
    for (int nt = 0; nt < 4; nt++) {
        int col = wn * 32 + nt * 8 + tg * 2;
        bool zcol = (col < 64);
        float bx = zcol ? __ldg(bias + col) : 0.f;
        float by = zcol ? __ldg(bias + col + 1) : 0.f;
        #pragma unroll
        for (int mt = 0; mt < 2; mt++) {
            #pragma unroll
            for (int hrow = 0; hrow < 2; hrow++) {
                int node = node_base + wm * 32 + mt * 16 + g + hrow * 8;
                if (node >= N) continue;
                float ox = c[mt][nt][hrow * 2 + 0] + bx;
                float oy = c[mt][nt][hrow * 2 + 1] + by;
                if (zcol) {
                    *(float2*)(g_z + node * 64 + col) = make_float2(ox, oy);
                } else {
                    __nv_bfloat162 p = __float22bfloat162_rn(make_float2(ox, oy));
                    *(__nv_bfloat162*)(g_bB + node * 64 + (col - 64)) = p;
                }
            }
        }
    }
}

// ---------------- launcher ----------------------------------------------------
extern "C" void kernel_launch(void* const* d_in, const int* in_sizes, int n_in,
                              void* d_out, int out_size) {
    const float* feat = (const float*)d_in[0];
    const int*   src  = (const int*)d_in[1];
    const int*   dst  = (const int*)d_in[2];
    const float* W0   = (const float*)d_in[3];
    const float* b0   = (const float*)d_in[4];
    const float* W1   = (const float*)d_in[5];
    const float* b1   = (const float*)d_in[6];
    const float* W2   = (const float*)d_in[7];
    const float* b2   = (const float*)d_in[8];
    float* out = (float*)d_out;

    const int smem128 = (128 * 136 + 64 * 132) * 4;   // 103,424 B
    cudaFuncSetAttribute(gemm_k<128, true, 1>, cudaFuncAttributeMaxDynamicSharedMemorySize, smem128);
    cudaFuncSetAttribute(gemm_k<128, true, 0>, cudaFuncAttributeMaxDynamicSharedMemorySize, smem128);
    cudaFuncSetAttribute(gemm2x_k, cudaFuncAttributeMaxDynamicSharedMemorySize, smem128);

    const int TB = 256;
    prep_count_k<<<(N * 64 + TB - 1) / TB, TB>>>(feat, W0, W1, W2, dst);
    scanA_k<<<NBLK, SCAN_B>>>();
    scanC_k<<<NBLK, SCAN_B>>>();
    scatter_k<<<(E + TB - 1) / TB, TB>>>(src, dst);

    int ablocks = (N + 7) / 8;       // 6250
    int gblocks = (N + 63) / 64;     // 782

    // layer 0: gather bf16 feat (g_bA); self = fp32 feat; out g_h0 + shadow g_bB
    agg_k<<<ablocks, TB>>>(0);
    gemm_k<128, true, 1><<<gblocks, TB, smem128>>>(feat, 0, b0, 1, 0);
    // layer 1: gather g_bB; self = g_h0; out g_h1
    agg_k<<<ablocks, TB>>>(1);
    gemm_k<128, true, 0><<<gblocks, TB, smem128>>>(nullptr, 1, b1, 2, 1);
    // layer 2 (projection-first): [z2|y2] = h2 @ [W2_top|W2_bot]; 64-dim gather + add
    gemm2x_k<<<gblocks, TB, smem128>>>(b2);
    agg64_k<<<ablocks, TB>>>(out);
}